// round 6
// baseline (speedup 1.0000x reference)
#include <cuda_runtime.h>

#define EPS_VAL   1e-5f
#define NTHREADS  320      // 10 warps; supports dim up to 1280 (296 float4s used here)
#define MAXVEC    320
#define NGROUPS   4

__global__ void __launch_bounds__(NTHREADS)
eqln_kernel(const float* __restrict__ x,
            const float* __restrict__ weight,
            const float* __restrict__ bias,
            const int*   __restrict__ group_idx,
            const int*   __restrict__ irrep_idx,
            const int*   __restrict__ scalar_indices,
            float*       __restrict__ out,
            int np, int dim, int nscalar)
{
    __shared__ float4 s_w [MAXVEC];   // weight[irrep_idx[i]] per element
    __shared__ float4 s_b [MAXVEC];   // bias scattered to full dim
    __shared__ float4 s_sf[MAXVEC];   // 1.0 on scalar positions else 0.0
    __shared__ int    s_g [MAXVEC];   // group id per float4 (groups are 16B-aligned)
    __shared__ float  s_cnt[NGROUPS], s_scnt[NGROUPS], s_invcnt[NGROUPS];
    __shared__ float  s_invsc;
    __shared__ float  s_ssq [2][NGROUPS];   // double-buffered accumulators
    __shared__ float  s_ssum[2][NGROUPS];

    const int tid  = threadIdx.x;
    const int nvec = dim >> 2;

    // ---------------- per-block metadata setup (amortized over ~90 rows) --------
    if (tid < NGROUPS) { s_cnt[tid] = 0.f; s_scnt[tid] = 0.f; }
    __syncthreads();

    for (int i = tid; i < dim; i += NTHREADS) {
        int g = group_idx[i];
        atomicAdd(&s_cnt[g], 1.f);
        ((float*)s_w )[i] = weight[irrep_idx[i]];
        ((float*)s_b )[i] = 0.f;
        ((float*)s_sf)[i] = 0.f;
        if ((i & 3) == 0) s_g[i >> 2] = g;
    }
    __syncthreads();
    for (int k = tid; k < nscalar; k += NTHREADS) {
        int idx = scalar_indices[k];
        ((float*)s_b )[idx] = bias[k];
        ((float*)s_sf)[idx] = 1.f;
        atomicAdd(&s_scnt[group_idx[idx]], 1.f);
    }
    __syncthreads();
    if (tid < NGROUPS) s_invcnt[tid] = 1.f / s_cnt[tid];
    if (tid == 0)
        s_invsc = 1.f / (s_scnt[0] + s_scnt[1] + s_scnt[2] + s_scnt[3]);
    __syncthreads();

    // ---------------- hoist row-invariant state into registers ------------------
    const bool act = (tid < nvec);
    const int  g   = act ? s_g[tid] : (NGROUPS - 1);
    float4 w4  = make_float4(0.f, 0.f, 0.f, 0.f);
    float4 b4  = w4, sf4 = w4;
    if (act) { w4 = s_w[tid]; b4 = s_b[tid]; sf4 = s_sf[tid]; }
    const float scg   = s_scnt[g];
    const float icg   = s_invcnt[g];
    const float invsc = s_invsc;

    const unsigned FULL = 0xffffffffu;
    const int lane = tid & 31;
    // Each warp spans at most two (contiguous) groups.
    const int gmin = __reduce_min_sync(FULL, g);
    const int gmax = __reduce_max_sync(FULL, g);

    // ---------------- persistent grid-stride row loop with prefetch -------------
    const size_t stride_elems = (size_t)gridDim.x * (size_t)dim;
    int row = blockIdx.x;
    const float* xp = x + (size_t)row * dim + 4 * tid;
    float4 v = make_float4(0.f, 0.f, 0.f, 0.f);
    if (row < np && act) v = *(const float4*)xp;

    int p = 0;
    while (row < np) {
        const int nrow = row + gridDim.x;
        const float* xpn = xp + stride_elems;
        float4 vn = make_float4(0.f, 0.f, 0.f, 0.f);
        if (nrow < np && act) vn = *(const float4*)xpn;   // prefetch next row

        // single-pass statistics on raw x:
        //   ssq  -> sum of x^2 (per group)
        //   ssum -> sum of x over scalar positions (per group)
        float ssq  = v.x * v.x + v.y * v.y + v.z * v.z + v.w * v.w;
        float ssum = v.x * sf4.x + v.y * sf4.y + v.z * sf4.z + v.w * sf4.w;

        if (tid < NGROUPS) { s_ssq[p][tid] = 0.f; s_ssum[p][tid] = 0.f; }
        __syncthreads();

        float sq_lo = (g == gmin) ? ssq  : 0.f;
        float su_lo = (g == gmin) ? ssum : 0.f;
        #pragma unroll
        for (int o = 16; o > 0; o >>= 1) {
            sq_lo += __shfl_xor_sync(FULL, sq_lo, o);
            su_lo += __shfl_xor_sync(FULL, su_lo, o);
        }
        if (gmax != gmin) {
            float sq_hi = (g == gmax) ? ssq  : 0.f;
            float su_hi = (g == gmax) ? ssum : 0.f;
            #pragma unroll
            for (int o = 16; o > 0; o >>= 1) {
                sq_hi += __shfl_xor_sync(FULL, sq_hi, o);
                su_hi += __shfl_xor_sync(FULL, su_hi, o);
            }
            if (lane == 0) {
                atomicAdd(&s_ssq [p][gmax], sq_hi);
                atomicAdd(&s_ssum[p][gmax], su_hi);
            }
        }
        if (lane == 0) {
            atomicAdd(&s_ssq [p][gmin], sq_lo);
            atomicAdd(&s_ssum[p][gmin], su_lo);
        }
        __syncthreads();

        if (act) {
            const float m  = (s_ssum[p][0] + s_ssum[p][1] +
                              s_ssum[p][2] + s_ssum[p][3]) * invsc;
            const float gs = s_ssum[p][g];
            // sum_g (x - m*sf)^2 = ssq_g - 2m*ssum_g + m^2*scount_g
            const float var = (s_ssq[p][g] - 2.f * m * gs + m * m * scg) * icg;
            const float rn  = rsqrtf(var + EPS_VAL);
            float4 o;
            o.x = (v.x - m * sf4.x) * rn * w4.x + b4.x;
            o.y = (v.y - m * sf4.y) * rn * w4.y + b4.y;
            o.z = (v.z - m * sf4.z) * rn * w4.z + b4.z;
            o.w = (v.w - m * sf4.w) * rn * w4.w + b4.w;
            *(float4*)(out + (size_t)row * dim + 4 * tid) = o;
        }

        v = vn; xp = xpn; row = nrow; p ^= 1;
    }
}

extern "C" void kernel_launch(void* const* d_in, const int* in_sizes, int n_in,
                              void* d_out, int out_size)
{
    const float* x              = (const float*)d_in[0];
    const float* weight         = (const float*)d_in[1];
    const float* bias           = (const float*)d_in[2];
    const int*   group_idx      = (const int*)  d_in[3];
    const int*   irrep_idx      = (const int*)  d_in[4];
    const int*   scalar_indices = (const int*)  d_in[5];
    // d_in[6] = scalar_group, unused (N_SCALAR_GROUPS == 1)

    const int dim     = in_sizes[3];            // len(group_idx) == feature dim
    const int np      = in_sizes[0] / dim;      // number of points
    const int nscalar = in_sizes[5];

    int grid = 152 * 5;                         // persistent: 5 CTAs/SM on 152 SMs
    if (grid > np) grid = np;

    eqln_kernel<<<grid, NTHREADS>>>(x, weight, bias,
                                    group_idx, irrep_idx, scalar_indices,
                                    (float*)d_out, np, dim, nscalar);
}

// round 7
// speedup vs baseline: 1.5217x; 1.5217x over previous
#include <cuda_runtime.h>

#define EPS_VAL   1e-5f
#define NT        256            // 8 warps/block
#define WPB       8
#define MAXVEC    320
#define NG        4
#define VPT       10             // max float4 vectors per lane (dim <= 1280)

__device__ __forceinline__ float sel4(int g, float a, float b, float c, float d) {
    float lo = (g == 0) ? a : b;
    float hi = (g == 2) ? c : d;
    return (g < 2) ? lo : hi;
}

__global__ void __launch_bounds__(NT, 3)
eqln_kernel(const float* __restrict__ x,
            const float* __restrict__ weight,
            const float* __restrict__ bias,
            const int*   __restrict__ group_idx,
            const int*   __restrict__ irrep_idx,
            const int*   __restrict__ scalar_indices,
            float*       __restrict__ out,
            int np, int dim, int nscalar)
{
    __shared__ float4 s_w[MAXVEC];       // weight[irrep_idx[i]] per element
    __shared__ float4 s_b[MAXVEC];       // bias scattered to full dim (0 elsewhere)
    __shared__ int    s_gv[MAXVEC];      // group id per float4 (groups 16B-aligned)
    __shared__ float  s_cnt[NG], s_scnt[NG];

    const int tid  = threadIdx.x;
    const int nvec = dim >> 2;

    // ---------------- per-block metadata setup (amortized over many rows) -------
    if (tid < NG) { s_cnt[tid] = 0.f; s_scnt[tid] = 0.f; }
    __syncthreads();
    for (int i = tid; i < dim; i += NT) {
        int g = group_idx[i];
        atomicAdd(&s_cnt[g], 1.f);
        ((float*)s_w)[i] = weight[irrep_idx[i]];
        ((float*)s_b)[i] = 0.f;
        if ((i & 3) == 0) s_gv[i >> 2] = g;
    }
    __syncthreads();
    for (int k = tid; k < nscalar; k += NT) {
        int idx = scalar_indices[k];
        ((float*)s_b)[idx] = bias[k];
        atomicAdd(&s_scnt[group_idx[idx]], 1.f);
    }
    __syncthreads();

    // ---------------- hoist row-invariant state into registers ------------------
    const int lane = tid & 31;
    const int wid  = tid >> 5;

    int  gv [VPT];
    bool act[VPT];
    #pragma unroll
    for (int i = 0; i < VPT; i++) {
        int v  = lane + 32 * i;
        act[i] = (v < nvec);
        gv[i]  = act[i] ? s_gv[v] : 3;
    }
    float icnt[NG], iscnt[NG];
    #pragma unroll
    for (int g = 0; g < NG; g++) {
        icnt[g]  = 1.f / s_cnt[g];
        iscnt[g] = (s_scnt[g] > 0.f) ? (1.f / s_scnt[g]) : 0.f;   // 0 => non-scalar group
    }
    const float sc0 = s_scnt[0], sc1 = s_scnt[1], sc2 = s_scnt[2], sc3 = s_scnt[3];

    const unsigned FULL = 0xffffffffu;
    const int totw = gridDim.x * WPB;

    // ---------------- warp-per-row main loop: NO barriers, no shared atomics ----
    for (int row = blockIdx.x * WPB + wid; row < np; row += totw) {
        const float4* xr = (const float4*)(x + (size_t)row * dim);

        float4 v[VPT];
        #pragma unroll
        for (int i = 0; i < VPT; i++)
            v[i] = act[i] ? xr[lane + 32 * i] : make_float4(0.f, 0.f, 0.f, 0.f);

        // per-thread per-group partials: a = sum x^2, u = sum x
        float a0 = 0.f, a1 = 0.f, a2 = 0.f, a3 = 0.f;
        float u0 = 0.f, u1 = 0.f, u2 = 0.f, u3 = 0.f;
        #pragma unroll
        for (int i = 0; i < VPT; i++) {
            float4 t = v[i];
            float s2 = t.x * t.x + t.y * t.y + t.z * t.z + t.w * t.w;
            float s1 = t.x + t.y + t.z + t.w;
            int g = gv[i];
            if      (g == 0) { a0 += s2; u0 += s1; }
            else if (g == 1) { a1 += s2; u1 += s1; }
            else if (g == 2) { a2 += s2; u2 += s1; }
            else             { a3 += s2; u3 += s1; }
        }

        // one butterfly: 8 independent chains, every lane ends with full sums
        #pragma unroll
        for (int o = 16; o > 0; o >>= 1) {
            a0 += __shfl_xor_sync(FULL, a0, o);
            a1 += __shfl_xor_sync(FULL, a1, o);
            a2 += __shfl_xor_sync(FULL, a2, o);
            a3 += __shfl_xor_sync(FULL, a3, o);
            u0 += __shfl_xor_sync(FULL, u0, o);
            u1 += __shfl_xor_sync(FULL, u1, o);
            u2 += __shfl_xor_sync(FULL, u2, o);
            u3 += __shfl_xor_sync(FULL, u3, o);
        }

        // per-group stats (every lane computes redundantly; 4 MUFU/lane is cheap)
        // m_g = scalar-mean (0 for non-scalar groups)
        // var_g = (ssq - m*(2*ssum - m*scnt)) / cnt
        float m0 = u0 * iscnt[0], m1 = u1 * iscnt[1];
        float m2 = u2 * iscnt[2], m3 = u3 * iscnt[3];
        float r0 = rsqrtf((a0 - m0 * (2.f * u0 - m0 * sc0)) * icnt[0] + EPS_VAL);
        float r1 = rsqrtf((a1 - m1 * (2.f * u1 - m1 * sc1)) * icnt[1] + EPS_VAL);
        float r2 = rsqrtf((a2 - m2 * (2.f * u2 - m2 * sc2)) * icnt[2] + EPS_VAL);
        float r3 = rsqrtf((a3 - m3 * (2.f * u3 - m3 * sc3)) * icnt[3] + EPS_VAL);

        float4* orow = (float4*)(out + (size_t)row * dim);
        #pragma unroll
        for (int i = 0; i < VPT; i++) {
            if (act[i]) {
                int g = gv[i];
                float mm = sel4(g, m0, m1, m2, m3);
                float rr = sel4(g, r0, r1, r2, r3);
                int vi = lane + 32 * i;
                float4 w = s_w[vi];
                float4 b = s_b[vi];
                float4 t = v[i];
                float4 o;
                o.x = (t.x - mm) * rr * w.x + b.x;
                o.y = (t.y - mm) * rr * w.y + b.y;
                o.z = (t.z - mm) * rr * w.z + b.z;
                o.w = (t.w - mm) * rr * w.w + b.w;
                orow[vi] = o;
            }
        }
    }
}

extern "C" void kernel_launch(void* const* d_in, const int* in_sizes, int n_in,
                              void* d_out, int out_size)
{
    const float* x              = (const float*)d_in[0];
    const float* weight         = (const float*)d_in[1];
    const float* bias           = (const float*)d_in[2];
    const int*   group_idx      = (const int*)  d_in[3];
    const int*   irrep_idx      = (const int*)  d_in[4];
    const int*   scalar_indices = (const int*)  d_in[5];
    // d_in[6] = scalar_group, unused (each scalar group is centered by its own mean)

    const int dim     = in_sizes[3];            // len(group_idx) == feature dim
    const int np      = in_sizes[0] / dim;      // number of points
    const int nscalar = in_sizes[5];

    int grid = 152 * 3;                         // 3 resident blocks/SM (reg-limited), 1 wave
    int maxb = (np + WPB - 1) / WPB;
    if (grid > maxb) grid = maxb;

    eqln_kernel<<<grid, NT>>>(x, weight, bias,
                              group_idx, irrep_idx, scalar_indices,
                              (float*)d_out, np, dim, nscalar);
}